// round 6
// baseline (speedup 1.0000x reference)
#include <cuda_runtime.h>
#include <math.h>

#define FDIM 256
#define BMAX 1024
#define NMAX 1048576
#define CHK 32            // k-chunk size for MLP W staging
#define SWS 34            // smem stride per W row chunk (32 data + 2 pad, even for ull align)

typedef unsigned long long ull;

// ---------------- scratch (static device globals; no allocation) ----------------
__device__ __align__(128) float g_kq [BMAX * FDIM];
__device__ __align__(128) float g_vm [BMAX * FDIM];
__device__ __align__(128) float g_dot[NMAX];
__device__ __align__(128) float g_smax[BMAX];
__device__ __align__(128) float g_inv [BMAX];

__device__ __forceinline__ float actf(float x) {
    return x / (1.0f + expf(-1.702f * x));
}
__device__ __forceinline__ ull ffma2(ull a, ull b, ull c) {
    ull d;
    asm("fma.rn.f32x2 %0, %1, %2, %3;" : "=l"(d) : "l"(a), "l"(b), "l"(c));
    return d;
}
__device__ __forceinline__ float pairsum(ull v) {
    float2 f = *(float2*)&v;
    return f.x + f.y;
}
__device__ __forceinline__ ull dup2(float w) {
    ull d;
    asm("mov.b64 %0, {%1, %1};" : "=l"(d) : "f"(w));
    return d;
}
__device__ __forceinline__ float dot4(float4 a, float4 b) {
    return a.x * b.x + a.y * b.y + a.z * b.z + a.w * b.w;
}

// ================= fused resMLP chain =================
// Block = 8 molecule rows through the whole chain. blockIdx.y: 0=k branch
// (incl. trailing @Wq), 1=v branch. Thread c owns output column c.
// W staged in 32-k chunks, double-buffered (regs -> smem), coalesced LDG.

// prefetch one 256x32 W chunk into 8 float4 regs (coalesced)
__device__ __forceinline__ void prefetchW(const float* __restrict__ W, int k0,
                                          int t, float4 pf[8]) {
    int lane = t & 31, w = t >> 5;
    int rsub = lane >> 3;        // 0..3
    int f4   = lane & 7;         // float4 index along 32-k chunk
    #pragma unroll
    for (int i = 0; i < 8; i++) {
        int row = w * 32 + i * 4 + rsub;
        pf[i] = *(const float4*)(W + (size_t)row * FDIM + k0 + f4 * 4);
    }
}
__device__ __forceinline__ void storeW(float* sW, int t, const float4 pf[8]) {
    int lane = t & 31, w = t >> 5;
    int rsub = lane >> 3;
    int f4   = lane & 7;
    #pragma unroll
    for (int i = 0; i < 8; i++) {
        int row = w * 32 + i * 4 + rsub;
        float* d = sW + row * SWS + f4 * 4;
        *(float2*)(d)     = make_float2(pf[i].x, pf[i].y);
        *(float2*)(d + 2) = make_float2(pf[i].z, pf[i].w);
    }
}
// accumulate one 32-k chunk: acc[r] += A[r][k0..] * sW[c][..]
__device__ __forceinline__ void gemm_chunk(const float* sW, const float* A,
                                           int c, int k0, ull acc[8]) {
    const float* wr = sW + c * SWS;
    #pragma unroll
    for (int kk = 0; kk < CHK / 4; kk++) {       // 4 k per iter
        ull w0 = *(const ull*)(wr + kk * 4);
        ull w1 = *(const ull*)(wr + kk * 4 + 2);
        #pragma unroll
        for (int r = 0; r < 8; r++) {
            ulonglong2 a = *(const ulonglong2*)(A + r * FDIM + k0 + kk * 4);
            acc[r] = ffma2(a.x, w0, acc[r]);
            acc[r] = ffma2(a.y, w1, acc[r]);
        }
    }
}
// one full 256x256 layer, double-buffered: o[r] = A[r,:] . W[c,:]
// (caller guarantees A is written; first internal barrier covers A visibility)
__device__ __forceinline__ void layer(const float* __restrict__ W,
                                      const float* A, float* sW0, float* sW1,
                                      int c, int t, float o[8]) {
    float4 pf[8];
    prefetchW(W, 0, t, pf);
    storeW(sW0, t, pf);
    __syncthreads();
    ull acc[8] = {0, 0, 0, 0, 0, 0, 0, 0};
    #pragma unroll
    for (int ch = 0; ch < 8; ch++) {
        float* cur = (ch & 1) ? sW1 : sW0;
        float* nxt = (ch & 1) ? sW0 : sW1;
        if (ch < 7) prefetchW(W, (ch + 1) * CHK, t, pf);
        gemm_chunk(cur, A, c, ch * CHK, acc);
        if (ch < 7) {
            storeW(nxt, t, pf);
            __syncthreads();
        }
    }
    #pragma unroll
    for (int r = 0; r < 8; r++) o[r] = pairsum(acc[r]);
}

__global__ void fused_mlp_kernel(const float* __restrict__ E,
                      const float* __restrict__ Wkf, const float* __restrict__ bkf,
                      const float* __restrict__ Wvf,
                      const float* __restrict__ kW1, const float* __restrict__ kb1,
                      const float* __restrict__ kW2, const float* __restrict__ kb2,
                      const float* __restrict__ kWo, const float* __restrict__ kbo,
                      const float* __restrict__ vW1, const float* __restrict__ vW2,
                      const float* __restrict__ vWo, const float* __restrict__ Wq,
                      float* __restrict__ kq, float* __restrict__ vm,
                      int B) {
    extern __shared__ __align__(16) float smdyn[];
    float* sW0  = smdyn;                              // 256*34
    float* sW1  = sW0 + 256 * SWS;                    // 256*34
    float* bufA = sW1 + 256 * SWS;                    // 8*256
    float* bufB = bufA + 8 * FDIM;                    // 8*256 (aliased as kmT)
    __shared__ float Es[8];

    int c = threadIdx.x;
    int isK = (blockIdx.y == 0);
    int row0 = blockIdx.x * 8;

    if (c < 8) Es[c] = (row0 + c < B) ? E[row0 + c] : 0.f;
    __syncthreads();

    float wf_c = isK ? Wkf[c] : Wvf[c];
    float bf_c = isK ? bkf[c] : 0.f;
    #pragma unroll
    for (int r = 0; r < 8; r++)
        bufA[r * FDIM + c] = actf(Es[r] * wf_c + bf_c);
    // layer() first barrier covers these writes

    float o[8];

    // L1: t1 = act(a0 @ W1^T + b1)
    layer(isK ? kW1 : vW1, bufA, sW0, sW1, c, threadIdx.x, o);
    {
        float b1 = isK ? kb1[c] : 0.f;
        #pragma unroll
        for (int r = 0; r < 8; r++)
            bufB[r * FDIM + c] = actf(o[r] + b1);
    }

    // L2: ar = act(h0 + t1 @ W2^T + b2)
    layer(isK ? kW2 : vW2, bufB, sW0, sW1, c, threadIdx.x, o);
    {
        float b2 = isK ? kb2[c] : 0.f;
        #pragma unroll
        for (int r = 0; r < 8; r++)
            bufA[r * FDIM + c] = actf(o[r] + b2 + (Es[r] * wf_c + bf_c));
    }

    // L3: mol = ar @ Wo^T + bo
    layer(isK ? kWo : vWo, bufA, sW0, sW1, c, threadIdx.x, o);

    if (!isK) {
        #pragma unroll
        for (int r = 0; r < 8; r++)
            if (row0 + r < B) vm[(size_t)(row0 + r) * FDIM + c] = o[r];
        return;
    }

    // kmT[c][r] = km (transposed), in bufB
    float* kmT = bufB;
    __syncthreads();                      // all gemm reads of bufB finished
    {
        float bo = kbo[c];
        #pragma unroll
        for (int r = 0; r < 8; r++)
            kmT[c * 8 + r] = o[r] + bo;
    }
    __syncthreads();

    // L4: kq[r][f] = sum_cc km[r][cc] * Wq[cc][f]; Wq column reads coalesced
    ull acc[4] = {0, 0, 0, 0};
    const float* __restrict__ wcol = Wq + c;
    #pragma unroll 4
    for (int cc = 0; cc < FDIM; cc++) {
        ulonglong2 a01 = *(const ulonglong2*)(kmT + cc * 8);
        ulonglong2 a23 = *(const ulonglong2*)(kmT + cc * 8 + 4);
        ull wd = dup2(__ldg(wcol + (size_t)cc * FDIM));
        acc[0] = ffma2(a01.x, wd, acc[0]);
        acc[1] = ffma2(a01.y, wd, acc[1]);
        acc[2] = ffma2(a23.x, wd, acc[2]);
        acc[3] = ffma2(a23.y, wd, acc[3]);
    }
    #pragma unroll
    for (int p = 0; p < 4; p++) {
        float2 f2 = *(float2*)&acc[p];
        int r = 2 * p;
        if (row0 + r < B)     kq[(size_t)(row0 + r) * FDIM + c]     = f2.x;
        if (row0 + r + 1 < B) kq[(size_t)(row0 + r + 1) * FDIM + c] = f2.y;
    }
}

// ---------------- seg helpers (int32 buffer that may really be int64) ----------------
__device__ __forceinline__ int seg_is64(const int* __restrict__ s, int N) {
    return s[N - 1] == 0;   // sorted, max=B-1>0; int64 LE high word at N-1 is 0
}

// ---------------- dot pass: 32 rows/warp, kq register-cached, x pipelined ------------
__global__ void dot_kernel(const float4* __restrict__ x,
                           const int* __restrict__ seg32,
                           const float* __restrict__ kq,
                           float* __restrict__ dotv,
                           int N) {
    int gw   = (blockIdx.x * blockDim.x + threadIdx.x) >> 5;
    int lane = threadIdx.x & 31;
    int row0 = gw * 32;
    if (row0 >= N) return;
    int st = seg_is64(seg32, N) ? 2 : 1;
    int nrows = N - row0; if (nrows > 32) nrows = 32;

    int myrow = row0 + lane;
    int rload = myrow < N ? myrow : N - 1;
    int bl = seg32[(size_t)rload * st];

    int bcur = -1;
    float4 k0, k1;
    float myres = 0.f;

    // prefetch row 0
    const float4* xr = x + (size_t)row0 * 64;
    float4 a0 = xr[lane], a1 = xr[lane + 32];

    for (int r = 0; r < nrows; r++) {
        // prefetch next row while computing this one
        float4 n0, n1;
        if (r + 1 < nrows) {
            const float4* xn = x + (size_t)(row0 + r + 1) * 64;
            n0 = xn[lane]; n1 = xn[lane + 32];
        }
        int b = __shfl_sync(0xffffffffu, bl, r);
        if (b != bcur) {
            const float4* kr = (const float4*)kq + (size_t)b * 64;
            k0 = kr[lane]; k1 = kr[lane + 32];
            bcur = b;
        }
        float s = dot4(a0, k0) + dot4(a1, k1);
        #pragma unroll
        for (int o = 16; o; o >>= 1) s += __shfl_xor_sync(0xffffffffu, s, o);
        if (lane == r) myres = s;
        a0 = n0; a1 = n1;
    }
    if (myrow < N) dotv[myrow] = myres;
}

// ---------------- segment reduce (deterministic, per-segment block) ----------------
__device__ __forceinline__ int lowerb(const int* __restrict__ s, int n, int v, int st) {
    int lo = 0, hi = n;
    while (lo < hi) {
        int mid = (lo + hi) >> 1;
        if (s[(size_t)mid * st] < v) lo = mid + 1; else hi = mid;
    }
    return lo;
}

__global__ void segreduce_kernel(const int* __restrict__ seg32,
                                 const float* __restrict__ dotv,
                                 float* __restrict__ smax,
                                 float* __restrict__ invnorm,
                                 int N, float scale) {
    __shared__ float red[256];
    __shared__ int sse[2];
    int b = blockIdx.x;
    int t = threadIdx.x;
    if (t == 0) {
        int st = seg_is64(seg32, N) ? 2 : 1;
        sse[0] = lowerb(seg32, N, b, st);
        sse[1] = lowerb(seg32, N, b + 1, st);
    }
    __syncthreads();
    int start = sse[0], end = sse[1];

    float m = -3.4e38f;
    for (int i = start + t; i < end; i += 256) m = fmaxf(m, dotv[i]);
    red[t] = m;
    __syncthreads();
    #pragma unroll
    for (int s = 128; s; s >>= 1) {
        if (t < s) red[t] = fmaxf(red[t], red[t + s]);
        __syncthreads();
    }
    float mx = red[0];
    __syncthreads();

    float ss = 0.f;
    for (int i = start + t; i < end; i += 256) ss += expf((dotv[i] - mx) * scale);
    red[t] = ss;
    __syncthreads();
    #pragma unroll
    for (int s = 128; s; s >>= 1) {
        if (t < s) red[t] += red[t + s];
        __syncthreads();
    }
    if (t == 0) {
        smax[b] = mx;
        invnorm[b] = 1.f / (red[0] + 1e-8f);
    }
}

// ---------------- output pass: 32 rows per warp, vm register-cached ----------------
__global__ void out_kernel(const float* __restrict__ dotv,
                           const int* __restrict__ seg32,
                           const float* __restrict__ vm,
                           const float* __restrict__ smax,
                           const float* __restrict__ invnorm,
                           float4* __restrict__ out,
                           int N, float scale) {
    int gw   = (blockIdx.x * blockDim.x + threadIdx.x) >> 5;
    int lane = threadIdx.x & 31;
    int row0 = gw * 32;
    if (row0 >= N) return;
    int st = seg_is64(seg32, N) ? 2 : 1;

    int myrow = row0 + lane;
    int bl = 0; float cl = 0.f;
    if (myrow < N) {
        bl = seg32[(size_t)myrow * st];
        cl = expf((dotv[myrow] - smax[bl]) * scale) * invnorm[bl];
    }

    int nrows = N - row0; if (nrows > 32) nrows = 32;
    int bcur = -1;
    float4 v0, v1;
    for (int r = 0; r < nrows; r++) {
        int b     = __shfl_sync(0xffffffffu, bl, r);
        float cf  = __shfl_sync(0xffffffffu, cl, r);
        if (b != bcur) {
            const float4* vr = (const float4*)vm + (size_t)b * 64;
            v0 = vr[lane];
            v1 = vr[lane + 32];
            bcur = b;
        }
        float4 o0 = make_float4(v0.x * cf, v0.y * cf, v0.z * cf, v0.w * cf);
        float4 o1 = make_float4(v1.x * cf, v1.y * cf, v1.z * cf, v1.w * cf);
        float4* orow = out + (size_t)(row0 + r) * 64;
        orow[lane]      = o0;
        orow[lane + 32] = o1;
    }
}

// ---------------- launcher ----------------
extern "C" void kernel_launch(void* const* d_in, const int* in_sizes, int n_in,
                              void* d_out, int out_size) {
    int sh = (n_in >= 17) ? 0 : 1;
    const float* x    = (const float*)d_in[0];
    const float* E    = (const float*)d_in[1];
    const int*   seg  = (const int*)  d_in[3 - sh];
    const float* Wq   = (const float*)d_in[4 - sh];
    const float* Wkf  = (const float*)d_in[5 - sh];
    const float* bkf  = (const float*)d_in[6 - sh];
    const float* Wvf  = (const float*)d_in[7 - sh];
    const float* kW1  = (const float*)d_in[8 - sh];
    const float* kb1  = (const float*)d_in[9 - sh];
    const float* kW2  = (const float*)d_in[10 - sh];
    const float* kb2  = (const float*)d_in[11 - sh];
    const float* kWo  = (const float*)d_in[12 - sh];
    const float* kbo  = (const float*)d_in[13 - sh];
    const float* vW1  = (const float*)d_in[14 - sh];
    const float* vW2  = (const float*)d_in[15 - sh];
    const float* vWo  = (const float*)d_in[16 - sh];

    int B = in_sizes[1];
    int N = in_sizes[3 - sh];
    float scale = 1.f / 16.f;   // 1/sqrt(256)

    float *kq, *vm, *dotv, *smax, *inv;
    cudaGetSymbolAddress((void**)&kq,  g_kq);
    cudaGetSymbolAddress((void**)&vm,  g_vm);
    cudaGetSymbolAddress((void**)&dotv, g_dot);
    cudaGetSymbolAddress((void**)&smax, g_smax);
    cudaGetSymbolAddress((void**)&inv,  g_inv);

    // 1) whole resMLP chain (both branches) in one launch
    const int MLP_SMEM = (2 * 256 * SWS + 2 * 8 * FDIM) * (int)sizeof(float); // 86016
    cudaFuncSetAttribute(fused_mlp_kernel, cudaFuncAttributeMaxDynamicSharedMemorySize, MLP_SMEM);
    dim3 mgrid((B + 7) / 8, 2);
    fused_mlp_kernel<<<mgrid, 256, MLP_SMEM>>>(E, Wkf, bkf, Wvf,
                                               kW1, kb1, kW2, kb2, kWo, kbo,
                                               vW1, vW2, vWo, Wq,
                                               kq, vm, B);

    // 2) dot pass: 32 rows per warp, kq register-cached
    {
        int warps = (N + 31) / 32;
        int blocks = (warps * 32 + 255) / 256;
        dot_kernel<<<blocks, 256>>>((const float4*)x, seg, kq, dotv, N);
    }

    // 3) deterministic per-segment max + expsum
    segreduce_kernel<<<B, 256>>>(seg, dotv, smax, inv, N, scale);

    // 4) output pass: 32 rows per warp
    {
        int warps = (N + 31) / 32;
        int blocks = (warps * 32 + 255) / 256;
        out_kernel<<<blocks, 256>>>(dotv, seg, vm, smax, inv, (float4*)d_out, N, scale);
    }
}

// round 7
// speedup vs baseline: 1.1038x; 1.1038x over previous
#include <cuda_runtime.h>
#include <math.h>

#define FDIM 256
#define BMAX 1024
#define NMAX 1048576
#define CHK 32            // k-chunk for W staging
#define SWS 34            // smem stride per W row (32 data + 2 pad, even)

typedef unsigned long long ull;

// ---------------- scratch (static device globals; no allocation) ----------------
__device__ __align__(128) float g_kq [BMAX * FDIM];
__device__ __align__(128) float g_vm [BMAX * FDIM];
__device__ __align__(128) float g_dot[NMAX];
__device__ __align__(128) float g_smax[BMAX];
__device__ __align__(128) float g_inv [BMAX];

__device__ __forceinline__ float actf(float x) {
    return x / (1.0f + expf(-1.702f * x));
}
__device__ __forceinline__ ull ffma2(ull a, ull b, ull c) {
    ull d;
    asm("fma.rn.f32x2 %0, %1, %2, %3;" : "=l"(d) : "l"(a), "l"(b), "l"(c));
    return d;
}
__device__ __forceinline__ float pairsum(ull v) {
    float2 f = *(float2*)&v;
    return f.x + f.y;
}
__device__ __forceinline__ ull dup2(float w) {
    ull d;
    asm("mov.b64 %0, {%1, %1};" : "=l"(d) : "f"(w));
    return d;
}
__device__ __forceinline__ float dot4(float4 a, float4 b) {
    return a.x * b.x + a.y * b.y + a.z * b.z + a.w * b.w;
}

// ================= fused resMLP chain (4 rows/block for occupancy) =================
// grid ((B+3)/4, 2): y=0 k-branch (incl. trailing @Wq), y=1 v-branch.
// Thread c owns output column c for the block's 4 rows.

// stage W[0..255][k0..k0+31] -> sW[row*SWS + k] with coalesced LDG.128
__device__ __forceinline__ void stageW(const float* __restrict__ W, float* sW,
                                       int k0, int t) {
    #pragma unroll
    for (int i = 0; i < 8; i++) {
        int idx = i * 256 + t;
        int row = idx >> 3;
        int f4  = idx & 7;
        float4 v = *(const float4*)(W + (size_t)row * FDIM + k0 + f4 * 4);
        float* d = sW + row * SWS + f4 * 4;
        *(float2*)(d)     = make_float2(v.x, v.y);
        *(float2*)(d + 2) = make_float2(v.z, v.w);
    }
}

// one 256x256 layer for 4 rows: o[r] = A[r,:] . W[c,:]
__device__ __forceinline__ void layer4(const float* __restrict__ W,
                                       const float* A, float* sW,
                                       int c, int t, float o[4]) {
    ull acc[4] = {0, 0, 0, 0};
    #pragma unroll
    for (int ch = 0; ch < 8; ch++) {
        __syncthreads();                 // prior sW readers (and A writers, ch=0) done
        stageW(W, sW, ch * CHK, t);
        __syncthreads();
        const float* wr = sW + c * SWS;
        const float* ab = A + ch * CHK;
        #pragma unroll
        for (int kk = 0; kk < CHK / 2; kk++) {   // one k-pair per iter
            ull w = *(const ull*)(wr + kk * 2);
            #pragma unroll
            for (int r = 0; r < 4; r++) {
                ull a = *(const ull*)(ab + r * FDIM + kk * 2);
                acc[r] = ffma2(a, w, acc[r]);
            }
        }
    }
    #pragma unroll
    for (int r = 0; r < 4; r++) o[r] = pairsum(acc[r]);
}

__global__ void fused_mlp_kernel(const float* __restrict__ E,
                      const float* __restrict__ Wkf, const float* __restrict__ bkf,
                      const float* __restrict__ Wvf,
                      const float* __restrict__ kW1, const float* __restrict__ kb1,
                      const float* __restrict__ kW2, const float* __restrict__ kb2,
                      const float* __restrict__ kWo, const float* __restrict__ kbo,
                      const float* __restrict__ vW1, const float* __restrict__ vW2,
                      const float* __restrict__ vWo, const float* __restrict__ Wq,
                      float* __restrict__ kq, float* __restrict__ vm,
                      int B) {
    extern __shared__ __align__(16) float smdyn[];
    float* sW   = smdyn;                      // 256*34 = 8704 floats
    float* bufA = sW + 256 * SWS;             // 4*256
    float* bufB = bufA + 4 * FDIM;            // 4*256 (also kmT: [256 c][4 r])
    __shared__ float Es[4];

    int c = threadIdx.x;
    int isK = (blockIdx.y == 0);
    int row0 = blockIdx.x * 4;

    if (c < 4) Es[c] = (row0 + c < B) ? E[row0 + c] : 0.f;
    __syncthreads();

    float wf_c = isK ? Wkf[c] : Wvf[c];
    float bf_c = isK ? bkf[c] : 0.f;
    #pragma unroll
    for (int r = 0; r < 4; r++)
        bufA[r * FDIM + c] = actf(Es[r] * wf_c + bf_c);
    // layer4's first barrier covers these writes

    float o[4];

    // L1: t1 = act(a0 @ W1^T + b1)
    layer4(isK ? kW1 : vW1, bufA, sW, c, threadIdx.x, o);
    {
        float b1 = isK ? kb1[c] : 0.f;
        #pragma unroll
        for (int r = 0; r < 4; r++)
            bufB[r * FDIM + c] = actf(o[r] + b1);
    }

    // L2: ar = act(h0 + t1 @ W2^T + b2)
    layer4(isK ? kW2 : vW2, bufB, sW, c, threadIdx.x, o);
    {
        float b2 = isK ? kb2[c] : 0.f;
        #pragma unroll
        for (int r = 0; r < 4; r++)
            bufA[r * FDIM + c] = actf(o[r] + b2 + (Es[r] * wf_c + bf_c));
    }

    // L3: mol = ar @ Wo^T + bo
    layer4(isK ? kWo : vWo, bufA, sW, c, threadIdx.x, o);

    if (!isK) {
        #pragma unroll
        for (int r = 0; r < 4; r++)
            if (row0 + r < B) vm[(size_t)(row0 + r) * FDIM + c] = o[r];
        return;
    }

    // kmT[c][r] = km (transposed into bufB)
    float* kmT = bufB;
    __syncthreads();                  // L3 compute (readers of sW/bufA) done in all threads
    {
        float bo = kbo[c];
        #pragma unroll
        for (int r = 0; r < 4; r++)
            kmT[c * 4 + r] = o[r] + bo;
    }
    __syncthreads();

    // L4: kq[r][f] = sum_cc km[r][cc] * Wq[cc][f]; Wq reads lane-coalesced
    ull acc[2] = {0, 0};
    const float* __restrict__ wcol = Wq + c;
    #pragma unroll 4
    for (int cc = 0; cc < FDIM; cc++) {
        ulonglong2 a = *(const ulonglong2*)(kmT + cc * 4);   // rows 0..3 (broadcast)
        ull wd = dup2(__ldg(wcol + (size_t)cc * FDIM));
        acc[0] = ffma2(a.x, wd, acc[0]);
        acc[1] = ffma2(a.y, wd, acc[1]);
    }
    #pragma unroll
    for (int p = 0; p < 2; p++) {
        float2 f2 = *(float2*)&acc[p];
        int r = 2 * p;
        if (row0 + r < B)     kq[(size_t)(row0 + r) * FDIM + c]     = f2.x;
        if (row0 + r + 1 < B) kq[(size_t)(row0 + r + 1) * FDIM + c] = f2.y;
    }
}

// ---------------- seg helpers (int32 buffer that may really be int64) ----------------
__device__ __forceinline__ int seg_is64(const int* __restrict__ s, int N) {
    return s[N - 1] == 0;   // sorted, max=B-1>0; int64 LE high word at N-1 is 0
}

// ---------------- dot pass: 2 rows per warp, front-batched loads ----------------
__global__ void dot_kernel(const float4* __restrict__ x,
                           const int* __restrict__ seg32,
                           const float* __restrict__ kq,
                           float* __restrict__ dotv,
                           int N) {
    int gw   = (blockIdx.x * blockDim.x + threadIdx.x) >> 5;
    int lane = threadIdx.x & 31;
    int r0 = gw * 2;
    if (r0 >= N) return;
    int st = seg_is64(seg32, N) ? 2 : 1;
    bool two = (r0 + 1 < N);
    int b0 = seg32[(size_t)r0 * st];
    int b1 = two ? seg32[(size_t)(r0 + 1) * st] : b0;
    const float4* x0 = x + (size_t)r0 * 64;
    const float4* x1 = x + (size_t)(two ? r0 + 1 : r0) * 64;
    const float4* k0 = (const float4*)kq + (size_t)b0 * 64;
    const float4* k1 = (const float4*)kq + (size_t)b1 * 64;

    float4 a0 = x0[lane], a1 = x0[lane + 32];
    float4 a2 = x1[lane], a3 = x1[lane + 32];
    float4 c0 = k0[lane], c1 = k0[lane + 32];
    float4 c2 = k1[lane], c3 = k1[lane + 32];

    float s0 = dot4(a0, c0) + dot4(a1, c1);
    float s1 = dot4(a2, c2) + dot4(a3, c3);
    #pragma unroll
    for (int o = 16; o; o >>= 1) {
        s0 += __shfl_xor_sync(0xffffffffu, s0, o);
        s1 += __shfl_xor_sync(0xffffffffu, s1, o);
    }
    if (lane == 0) {
        dotv[r0] = s0;
        if (two) dotv[r0 + 1] = s1;
    }
}

// ---------------- segment reduce (deterministic, per-segment block) ----------------
__device__ __forceinline__ int lowerb(const int* __restrict__ s, int n, int v, int st) {
    int lo = 0, hi = n;
    while (lo < hi) {
        int mid = (lo + hi) >> 1;
        if (s[(size_t)mid * st] < v) lo = mid + 1; else hi = mid;
    }
    return lo;
}

__global__ void segreduce_kernel(const int* __restrict__ seg32,
                                 const float* __restrict__ dotv,
                                 float* __restrict__ smax,
                                 float* __restrict__ invnorm,
                                 int N, float scale) {
    __shared__ float red[256];
    __shared__ int sse[2];
    int b = blockIdx.x;
    int t = threadIdx.x;
    if (t == 0) {
        int st = seg_is64(seg32, N) ? 2 : 1;
        sse[0] = lowerb(seg32, N, b, st);
        sse[1] = lowerb(seg32, N, b + 1, st);
    }
    __syncthreads();
    int start = sse[0], end = sse[1];

    float m = -3.4e38f;
    for (int i = start + t; i < end; i += 256) m = fmaxf(m, dotv[i]);
    red[t] = m;
    __syncthreads();
    #pragma unroll
    for (int s = 128; s; s >>= 1) {
        if (t < s) red[t] = fmaxf(red[t], red[t + s]);
        __syncthreads();
    }
    float mx = red[0];
    __syncthreads();

    float ss = 0.f;
    for (int i = start + t; i < end; i += 256) ss += expf((dotv[i] - mx) * scale);
    red[t] = ss;
    __syncthreads();
    #pragma unroll
    for (int s = 128; s; s >>= 1) {
        if (t < s) red[t] += red[t + s];
        __syncthreads();
    }
    if (t == 0) {
        smax[b] = mx;
        invnorm[b] = 1.f / (red[0] + 1e-8f);
    }
}

// ---------------- output pass: 32 rows per warp, vm register-cached ----------------
__global__ void out_kernel(const float* __restrict__ dotv,
                           const int* __restrict__ seg32,
                           const float* __restrict__ vm,
                           const float* __restrict__ smax,
                           const float* __restrict__ invnorm,
                           float4* __restrict__ out,
                           int N, float scale) {
    int gw   = (blockIdx.x * blockDim.x + threadIdx.x) >> 5;
    int lane = threadIdx.x & 31;
    int row0 = gw * 32;
    if (row0 >= N) return;
    int st = seg_is64(seg32, N) ? 2 : 1;

    int myrow = row0 + lane;
    int bl = 0; float cl = 0.f;
    if (myrow < N) {
        bl = seg32[(size_t)myrow * st];
        cl = expf((dotv[myrow] - smax[bl]) * scale) * invnorm[bl];
    }

    int nrows = N - row0; if (nrows > 32) nrows = 32;
    int bcur = -1;
    float4 v0, v1;
    for (int r = 0; r < nrows; r++) {
        int b     = __shfl_sync(0xffffffffu, bl, r);
        float cf  = __shfl_sync(0xffffffffu, cl, r);
        if (b != bcur) {
            const float4* vr = (const float4*)vm + (size_t)b * 64;
            v0 = vr[lane];
            v1 = vr[lane + 32];
            bcur = b;
        }
        float4 o0 = make_float4(v0.x * cf, v0.y * cf, v0.z * cf, v0.w * cf);
        float4 o1 = make_float4(v1.x * cf, v1.y * cf, v1.z * cf, v1.w * cf);
        float4* orow = out + (size_t)(row0 + r) * 64;
        orow[lane]      = o0;
        orow[lane + 32] = o1;
    }
}

// ---------------- launcher ----------------
extern "C" void kernel_launch(void* const* d_in, const int* in_sizes, int n_in,
                              void* d_out, int out_size) {
    int sh = (n_in >= 17) ? 0 : 1;
    const float* x    = (const float*)d_in[0];
    const float* E    = (const float*)d_in[1];
    const int*   seg  = (const int*)  d_in[3 - sh];
    const float* Wq   = (const float*)d_in[4 - sh];
    const float* Wkf  = (const float*)d_in[5 - sh];
    const float* bkf  = (const float*)d_in[6 - sh];
    const float* Wvf  = (const float*)d_in[7 - sh];
    const float* kW1  = (const float*)d_in[8 - sh];
    const float* kb1  = (const float*)d_in[9 - sh];
    const float* kW2  = (const float*)d_in[10 - sh];
    const float* kb2  = (const float*)d_in[11 - sh];
    const float* kWo  = (const float*)d_in[12 - sh];
    const float* kbo  = (const float*)d_in[13 - sh];
    const float* vW1  = (const float*)d_in[14 - sh];
    const float* vW2  = (const float*)d_in[15 - sh];
    const float* vWo  = (const float*)d_in[16 - sh];

    int B = in_sizes[1];
    int N = in_sizes[3 - sh];
    float scale = 1.f / 16.f;   // 1/sqrt(256)

    float *kq, *vm, *dotv, *smax, *inv;
    cudaGetSymbolAddress((void**)&kq,  g_kq);
    cudaGetSymbolAddress((void**)&vm,  g_vm);
    cudaGetSymbolAddress((void**)&dotv, g_dot);
    cudaGetSymbolAddress((void**)&smax, g_smax);
    cudaGetSymbolAddress((void**)&inv,  g_inv);

    // 1) whole resMLP chain, 4 rows/block for occupancy (grid = 256 CTAs)
    const int MLP_SMEM = (256 * SWS + 2 * 4 * FDIM) * (int)sizeof(float);  // 43008 B
    cudaFuncSetAttribute(fused_mlp_kernel, cudaFuncAttributeMaxDynamicSharedMemorySize, MLP_SMEM);
    dim3 mgrid((B + 3) / 4, 2);
    fused_mlp_kernel<<<mgrid, 256, MLP_SMEM>>>(E, Wkf, bkf, Wvf,
                                               kW1, kb1, kW2, kb2, kWo, kbo,
                                               vW1, vW2, vWo, Wq,
                                               kq, vm, B);

    // 2) dot pass: 2 rows per warp
    {
        int warps = (N + 1) / 2;
        int blocks = (warps * 32 + 255) / 256;
        dot_kernel<<<blocks, 256>>>((const float4*)x, seg, kq, dotv, N);
    }

    // 3) deterministic per-segment max + expsum
    segreduce_kernel<<<B, 256>>>(seg, dotv, smax, inv, N, scale);

    // 4) output pass: 32 rows per warp
    {
        int warps = (N + 31) / 32;
        int blocks = (warps * 32 + 255) / 256;
        out_kernel<<<blocks, 256>>>(dotv, seg, vm, smax, inv, (float4*)d_out, N, scale);
    }
}

// round 8
// speedup vs baseline: 1.1410x; 1.0337x over previous
#include <cuda_runtime.h>
#include <math.h>

#define FDIM 256
#define BMAX 1024
#define NMAX 1048576
#define CHK 32            // k-chunk for W staging
#define SWS 34            // smem stride per W row (32 data + 2 pad, even)

typedef unsigned long long ull;

// ---------------- scratch (static device globals; no allocation) ----------------
__device__ __align__(128) float g_kq [BMAX * FDIM];
__device__ __align__(128) float g_vm [BMAX * FDIM];
__device__ __align__(128) float g_dot[NMAX];
__device__ __align__(128) float g_smax[BMAX];
__device__ __align__(128) float g_inv [BMAX];

__device__ __forceinline__ float actf(float x) {
    return x / (1.0f + expf(-1.702f * x));
}
__device__ __forceinline__ ull ffma2(ull a, ull b, ull c) {
    ull d;
    asm("fma.rn.f32x2 %0, %1, %2, %3;" : "=l"(d) : "l"(a), "l"(b), "l"(c));
    return d;
}
__device__ __forceinline__ float pairsum(ull v) {
    float2 f = *(float2*)&v;
    return f.x + f.y;
}
__device__ __forceinline__ ull dup2(float w) {
    ull d;
    asm("mov.b64 %0, {%1, %1};" : "=l"(d) : "f"(w));
    return d;
}
__device__ __forceinline__ float dot4(float4 a, float4 b) {
    return a.x * b.x + a.y * b.y + a.z * b.z + a.w * b.w;
}

// ================= fused resMLP chain (4 rows/block) =================
// grid ((B+3)/4, 2): y=0 k-branch (incl. trailing @Wq), y=1 v-branch.
// Thread c owns output column c for the block's 4 rows.

__device__ __forceinline__ void stageW(const float* __restrict__ W, float* sW,
                                       int k0, int t) {
    #pragma unroll
    for (int i = 0; i < 8; i++) {
        int idx = i * 256 + t;
        int row = idx >> 3;
        int f4  = idx & 7;
        float4 v = *(const float4*)(W + (size_t)row * FDIM + k0 + f4 * 4);
        float* d = sW + row * SWS + f4 * 4;
        *(float2*)(d)     = make_float2(v.x, v.y);
        *(float2*)(d + 2) = make_float2(v.z, v.w);
    }
}

__device__ __forceinline__ void layer4(const float* __restrict__ W,
                                       const float* A, float* sW,
                                       int c, int t, float o[4]) {
    ull acc[4] = {0, 0, 0, 0};
    #pragma unroll
    for (int ch = 0; ch < 8; ch++) {
        __syncthreads();
        stageW(W, sW, ch * CHK, t);
        __syncthreads();
        const float* wr = sW + c * SWS;
        const float* ab = A + ch * CHK;
        #pragma unroll
        for (int kk = 0; kk < CHK / 2; kk++) {
            ull w = *(const ull*)(wr + kk * 2);
            #pragma unroll
            for (int r = 0; r < 4; r++) {
                ull a = *(const ull*)(ab + r * FDIM + kk * 2);
                acc[r] = ffma2(a, w, acc[r]);
            }
        }
    }
    #pragma unroll
    for (int r = 0; r < 4; r++) o[r] = pairsum(acc[r]);
}

__global__ void fused_mlp_kernel(const float* __restrict__ E,
                      const float* __restrict__ Wkf, const float* __restrict__ bkf,
                      const float* __restrict__ Wvf,
                      const float* __restrict__ kW1, const float* __restrict__ kb1,
                      const float* __restrict__ kW2, const float* __restrict__ kb2,
                      const float* __restrict__ kWo, const float* __restrict__ kbo,
                      const float* __restrict__ vW1, const float* __restrict__ vW2,
                      const float* __restrict__ vWo, const float* __restrict__ Wq,
                      float* __restrict__ kq, float* __restrict__ vm,
                      int B) {
    extern __shared__ __align__(16) float smdyn[];
    float* sW   = smdyn;                      // 256*34
    float* bufA = sW + 256 * SWS;             // 4*256
    float* bufB = bufA + 4 * FDIM;            // 4*256 (also kmT)
    __shared__ float Es[4];

    int c = threadIdx.x;
    int isK = (blockIdx.y == 0);
    int row0 = blockIdx.x * 4;

    if (c < 4) Es[c] = (row0 + c < B) ? E[row0 + c] : 0.f;
    __syncthreads();

    float wf_c = isK ? Wkf[c] : Wvf[c];
    float bf_c = isK ? bkf[c] : 0.f;
    #pragma unroll
    for (int r = 0; r < 4; r++)
        bufA[r * FDIM + c] = actf(Es[r] * wf_c + bf_c);

    float o[4];

    layer4(isK ? kW1 : vW1, bufA, sW, c, threadIdx.x, o);
    {
        float b1 = isK ? kb1[c] : 0.f;
        #pragma unroll
        for (int r = 0; r < 4; r++)
            bufB[r * FDIM + c] = actf(o[r] + b1);
    }

    layer4(isK ? kW2 : vW2, bufB, sW, c, threadIdx.x, o);
    {
        float b2 = isK ? kb2[c] : 0.f;
        #pragma unroll
        for (int r = 0; r < 4; r++)
            bufA[r * FDIM + c] = actf(o[r] + b2 + (Es[r] * wf_c + bf_c));
    }

    layer4(isK ? kWo : vWo, bufA, sW, c, threadIdx.x, o);

    if (!isK) {
        #pragma unroll
        for (int r = 0; r < 4; r++)
            if (row0 + r < B) vm[(size_t)(row0 + r) * FDIM + c] = o[r];
        return;
    }

    float* kmT = bufB;
    __syncthreads();
    {
        float bo = kbo[c];
        #pragma unroll
        for (int r = 0; r < 4; r++)
            kmT[c * 4 + r] = o[r] + bo;
    }
    __syncthreads();

    // L4: kq[r][f] = sum_cc km[r][cc] * Wq[cc][f]; deep unroll for LDG MLP
    ull acc[2] = {0, 0};
    const float* __restrict__ wcol = Wq + c;
    #pragma unroll 16
    for (int cc = 0; cc < FDIM; cc++) {
        ulonglong2 a = *(const ulonglong2*)(kmT + cc * 4);
        ull wd = dup2(__ldg(wcol + (size_t)cc * FDIM));
        acc[0] = ffma2(a.x, wd, acc[0]);
        acc[1] = ffma2(a.y, wd, acc[1]);
    }
    #pragma unroll
    for (int p = 0; p < 2; p++) {
        float2 f2 = *(float2*)&acc[p];
        int r = 2 * p;
        if (row0 + r < B)     kq[(size_t)(row0 + r) * FDIM + c]     = f2.x;
        if (row0 + r + 1 < B) kq[(size_t)(row0 + r + 1) * FDIM + c] = f2.y;
    }
}

// ---------------- seg helpers (int32 buffer that may really be int64) ----------------
__device__ __forceinline__ int seg_is64(const int* __restrict__ s, int N) {
    return s[N - 1] == 0;   // sorted, max=B-1>0; int64 LE high word at N-1 is 0
}

// ---------------- dot pass: 32 rows/warp, kq register-cached ----------------
// Fast path (single segment spanning the warp's 32 rows, ~96% of warps):
// fully unrolled 8-row batches with ILP shfl trees, one coalesced store.
__global__ void dot_kernel(const float4* __restrict__ x,
                           const int* __restrict__ seg32,
                           const float* __restrict__ kq,
                           float* __restrict__ dotv,
                           int N) {
    int gw   = (blockIdx.x * blockDim.x + threadIdx.x) >> 5;
    int lane = threadIdx.x & 31;
    int row0 = gw * 32;
    if (row0 >= N) return;
    int st = seg_is64(seg32, N) ? 2 : 1;

    int rlast = row0 + 31 < N ? row0 + 31 : N - 1;
    int b0    = seg32[(size_t)row0 * st];
    int blast = seg32[(size_t)rlast * st];

    if (b0 == blast && row0 + 32 <= N) {
        const float4* kr = (const float4*)kq + (size_t)b0 * 64;
        float4 k0 = kr[lane], k1 = kr[lane + 32];
        float myres = 0.f;
        #pragma unroll
        for (int batch = 0; batch < 4; batch++) {
            float4 xa[8], xb[8];
            #pragma unroll
            for (int r = 0; r < 8; r++) {
                const float4* xr = x + (size_t)(row0 + batch * 8 + r) * 64;
                xa[r] = xr[lane];
                xb[r] = xr[lane + 32];
            }
            float s[8];
            #pragma unroll
            for (int r = 0; r < 8; r++)
                s[r] = dot4(xa[r], k0) + dot4(xb[r], k1);
            #pragma unroll
            for (int o = 16; o; o >>= 1) {
                #pragma unroll
                for (int r = 0; r < 8; r++)
                    s[r] += __shfl_xor_sync(0xffffffffu, s[r], o);
            }
            #pragma unroll
            for (int r = 0; r < 8; r++)
                if (lane == batch * 8 + r) myres = s[r];
        }
        dotv[row0 + lane] = myres;        // coalesced 128B store
    } else {
        // slow path: per-row, reload kq on segment change (rare)
        int nrows = N - row0; if (nrows > 32) nrows = 32;
        int myrow = row0 + lane;
        int rload = myrow < N ? myrow : N - 1;
        int bl = seg32[(size_t)rload * st];
        int bcur = -1;
        float4 k0, k1;
        float myres = 0.f;
        for (int r = 0; r < nrows; r++) {
            int b = __shfl_sync(0xffffffffu, bl, r);
            if (b != bcur) {
                const float4* kr = (const float4*)kq + (size_t)b * 64;
                k0 = kr[lane]; k1 = kr[lane + 32];
                bcur = b;
            }
            const float4* xr = x + (size_t)(row0 + r) * 64;
            float4 a0 = xr[lane], a1 = xr[lane + 32];
            float s = dot4(a0, k0) + dot4(a1, k1);
            #pragma unroll
            for (int o = 16; o; o >>= 1) s += __shfl_xor_sync(0xffffffffu, s, o);
            if (lane == r) myres = s;
        }
        if (myrow < N) dotv[myrow] = myres;
    }
}

// ---------------- segment reduce (deterministic, per-segment block) ----------------
__device__ __forceinline__ int lowerb(const int* __restrict__ s, int n, int v, int st) {
    int lo = 0, hi = n;
    while (lo < hi) {
        int mid = (lo + hi) >> 1;
        if (s[(size_t)mid * st] < v) lo = mid + 1; else hi = mid;
    }
    return lo;
}

__global__ void segreduce_kernel(const int* __restrict__ seg32,
                                 const float* __restrict__ dotv,
                                 float* __restrict__ smax,
                                 float* __restrict__ invnorm,
                                 int N, float scale) {
    __shared__ float red[256];
    __shared__ int sse[2];
    int b = blockIdx.x;
    int t = threadIdx.x;
    if (t == 0) {
        int st = seg_is64(seg32, N) ? 2 : 1;
        sse[0] = lowerb(seg32, N, b, st);
        sse[1] = lowerb(seg32, N, b + 1, st);
    }
    __syncthreads();
    int start = sse[0], end = sse[1];

    float m = -3.4e38f;
    for (int i = start + t; i < end; i += 256) m = fmaxf(m, dotv[i]);
    red[t] = m;
    __syncthreads();
    #pragma unroll
    for (int s = 128; s; s >>= 1) {
        if (t < s) red[t] = fmaxf(red[t], red[t + s]);
        __syncthreads();
    }
    float mx = red[0];
    __syncthreads();

    float ss = 0.f;
    for (int i = start + t; i < end; i += 256) ss += expf((dotv[i] - mx) * scale);
    red[t] = ss;
    __syncthreads();
    #pragma unroll
    for (int s = 128; s; s >>= 1) {
        if (t < s) red[t] += red[t + s];
        __syncthreads();
    }
    if (t == 0) {
        smax[b] = mx;
        invnorm[b] = 1.f / (red[0] + 1e-8f);
    }
}

// ---------------- output pass: 32 rows per warp, vm register-cached ----------------
__global__ void out_kernel(const float* __restrict__ dotv,
                           const int* __restrict__ seg32,
                           const float* __restrict__ vm,
                           const float* __restrict__ smax,
                           const float* __restrict__ invnorm,
                           float4* __restrict__ out,
                           int N, float scale) {
    int gw   = (blockIdx.x * blockDim.x + threadIdx.x) >> 5;
    int lane = threadIdx.x & 31;
    int row0 = gw * 32;
    if (row0 >= N) return;
    int st = seg_is64(seg32, N) ? 2 : 1;

    int myrow = row0 + lane;
    int bl = 0; float cl = 0.f;
    if (myrow < N) {
        bl = seg32[(size_t)myrow * st];
        cl = expf((dotv[myrow] - smax[bl]) * scale) * invnorm[bl];
    }

    int nrows = N - row0; if (nrows > 32) nrows = 32;
    int bcur = -1;
    float4 v0, v1;
    for (int r = 0; r < nrows; r++) {
        int b     = __shfl_sync(0xffffffffu, bl, r);
        float cf  = __shfl_sync(0xffffffffu, cl, r);
        if (b != bcur) {
            const float4* vr = (const float4*)vm + (size_t)b * 64;
            v0 = vr[lane];
            v1 = vr[lane + 32];
            bcur = b;
        }
        float4 o0 = make_float4(v0.x * cf, v0.y * cf, v0.z * cf, v0.w * cf);
        float4 o1 = make_float4(v1.x * cf, v1.y * cf, v1.z * cf, v1.w * cf);
        float4* orow = out + (size_t)(row0 + r) * 64;
        orow[lane]      = o0;
        orow[lane + 32] = o1;
    }
}

// ---------------- launcher ----------------
extern "C" void kernel_launch(void* const* d_in, const int* in_sizes, int n_in,
                              void* d_out, int out_size) {
    int sh = (n_in >= 17) ? 0 : 1;
    const float* x    = (const float*)d_in[0];
    const float* E    = (const float*)d_in[1];
    const int*   seg  = (const int*)  d_in[3 - sh];
    const float* Wq   = (const float*)d_in[4 - sh];
    const float* Wkf  = (const float*)d_in[5 - sh];
    const float* bkf  = (const float*)d_in[6 - sh];
    const float* Wvf  = (const float*)d_in[7 - sh];
    const float* kW1  = (const float*)d_in[8 - sh];
    const float* kb1  = (const float*)d_in[9 - sh];
    const float* kW2  = (const float*)d_in[10 - sh];
    const float* kb2  = (const float*)d_in[11 - sh];
    const float* kWo  = (const float*)d_in[12 - sh];
    const float* kbo  = (const float*)d_in[13 - sh];
    const float* vW1  = (const float*)d_in[14 - sh];
    const float* vW2  = (const float*)d_in[15 - sh];
    const float* vWo  = (const float*)d_in[16 - sh];

    int B = in_sizes[1];
    int N = in_sizes[3 - sh];
    float scale = 1.f / 16.f;   // 1/sqrt(256)

    float *kq, *vm, *dotv, *smax, *inv;
    cudaGetSymbolAddress((void**)&kq,  g_kq);
    cudaGetSymbolAddress((void**)&vm,  g_vm);
    cudaGetSymbolAddress((void**)&dotv, g_dot);
    cudaGetSymbolAddress((void**)&smax, g_smax);
    cudaGetSymbolAddress((void**)&inv,  g_inv);

    // 1) whole resMLP chain, 4 rows/block (grid = 256 CTAs)
    const int MLP_SMEM = (256 * SWS + 2 * 4 * FDIM) * (int)sizeof(float);  // 43008 B
    cudaFuncSetAttribute(fused_mlp_kernel, cudaFuncAttributeMaxDynamicSharedMemorySize, MLP_SMEM);
    dim3 mgrid((B + 3) / 4, 2);
    fused_mlp_kernel<<<mgrid, 256, MLP_SMEM>>>(E, Wkf, bkf, Wvf,
                                               kW1, kb1, kW2, kb2, kWo, kbo,
                                               vW1, vW2, vWo, Wq,
                                               kq, vm, B);

    // 2) dot pass: 32 rows per warp, kq register-cached, fast uniform path
    {
        int warps = (N + 31) / 32;
        int blocks = (warps * 32 + 255) / 256;
        dot_kernel<<<blocks, 256>>>((const float4*)x, seg, kq, dotv, N);
    }

    // 3) deterministic per-segment max + expsum
    segreduce_kernel<<<B, 256>>>(seg, dotv, smax, inv, N, scale);

    // 4) output pass: 32 rows per warp
    {
        int warps = (N + 31) / 32;
        int blocks = (warps * 32 + 255) / 256;
        out_kernel<<<blocks, 256>>>(dotv, seg, vm, smax, inv, (float4*)d_out, N, scale);
    }
}

// round 9
// speedup vs baseline: 1.1872x; 1.0405x over previous
#include <cuda_runtime.h>
#include <math.h>

#define FDIM 256
#define BMAX 1024
#define NMAX 1048576
#define WST 258           // sW stride in floats (256 data + 2 pad; (258 mod 32)=2 -> conflict-free LDS.64)

typedef unsigned long long ull;

// ---------------- scratch (static device globals; no allocation) ----------------
__device__ __align__(128) float g_t1k[BMAX * FDIM];
__device__ __align__(128) float g_t1v[BMAX * FDIM];
__device__ __align__(128) float g_rk [BMAX * FDIM];
__device__ __align__(128) float g_rv [BMAX * FDIM];
__device__ __align__(128) float g_km [BMAX * FDIM];
__device__ __align__(128) float g_vm [BMAX * FDIM];
__device__ __align__(128) float g_kq [BMAX * FDIM];
__device__ __align__(128) float g_wqT[FDIM * FDIM];
__device__ __align__(128) float g_dot[NMAX];
__device__ __align__(128) float g_smax[BMAX];
__device__ __align__(128) float g_inv [BMAX];

__device__ __forceinline__ float actf(float x) {
    return x / (1.0f + expf(-1.702f * x));
}
__device__ __forceinline__ ull ffma2(ull a, ull b, ull c) {
    ull d;
    asm("fma.rn.f32x2 %0, %1, %2, %3;" : "=l"(d) : "l"(a), "l"(b), "l"(c));
    return d;
}
__device__ __forceinline__ float pairsum(ull v) {
    float2 f = *(float2*)&v;
    return f.x + f.y;
}
__device__ __forceinline__ float dot4(float4 a, float4 b) {
    return a.x * b.x + a.y * b.y + a.z * b.z + a.w * b.w;
}

// ---------------- transpose 256x256 (for Wq) ----------------
__global__ void transpose256_kernel(const float* __restrict__ in, float* __restrict__ out) {
    __shared__ float tile[32][33];
    int bx = (blockIdx.x & 7) * 32;
    int by = (blockIdx.x >> 3) * 32;
    int tx = threadIdx.x & 31, ty = threadIdx.x >> 5;
    #pragma unroll
    for (int i = 0; i < 32; i += 8)
        tile[ty + i][tx] = in[(size_t)(by + ty + i) * 256 + bx + tx];
    __syncthreads();
    #pragma unroll
    for (int i = 0; i < 32; i += 8)
        out[(size_t)(bx + ty + i) * 256 + by + tx] = tile[tx][ty + i];
}

// ================= col-tiled layer GEMM =================
// C[row0+r][f0+c] = post( A[row0+r,:] . W[f0+c,:] + bias[f0+c] )
// grid: (8 colTiles, rowTiles, 2 branches).  block 256: warp = 4 rows, lane = col.
// mode bits: 1 = A is entry rank1 act(E*ewf+ebf); 2 = add rank1 residual
//            (E*ewf+ebf) in epilogue; 4 = apply act.
__global__ __launch_bounds__(256)
void layer_kernel(const float* __restrict__ A0, const float* __restrict__ A1,
                  const float* __restrict__ W0, const float* __restrict__ W1,
                  const float* __restrict__ b0, const float* __restrict__ b1,
                  const float* __restrict__ E,
                  const float* __restrict__ ef0, const float* __restrict__ eb0,
                  const float* __restrict__ ef1, const float* __restrict__ eb1,
                  float* __restrict__ C0, float* __restrict__ C1,
                  int B, int mode) {
    extern __shared__ __align__(16) float sm[];
    float* sW = sm;                 // 32 x WST
    float* sA = sm + 32 * WST;      // 32 x 256

    int br = blockIdx.z;
    const float* A    = br ? A1 : A0;
    const float* W    = br ? W1 : W0;
    const float* bias = br ? b1 : b0;
    const float* ewf  = br ? ef1 : ef0;
    const float* ebf  = br ? eb1 : eb0;
    float*       C    = br ? C1 : C0;

    int t    = threadIdx.x;
    int f0   = blockIdx.x * 32;
    int row0 = blockIdx.y * 32;

    // ---- stage W tile: rows f0..f0+31, all 256 k (coalesced) ----
    {
        const float4* W4 = (const float4*)W;
        #pragma unroll
        for (int i = 0; i < 8; i++) {
            int idx = i * 256 + t;      // 0..2047
            int row = idx >> 6;
            int k4  = idx & 63;
            float4 v = W4[(size_t)(f0 + row) * 64 + k4];
            float* d = sW + row * WST + k4 * 4;
            *(float2*)(d)     = make_float2(v.x, v.y);
            *(float2*)(d + 2) = make_float2(v.z, v.w);
        }
    }

    // ---- stage A tile: rows row0..row0+31 ----
    if (mode & 1) {
        // entry: sA[r][k] = act(E[row]*ewf[k] + ebf[k])
        const float4* ew4 = (const float4*)ewf;
        const float4* eb4 = (const float4*)ebf;
        #pragma unroll
        for (int i = 0; i < 8; i++) {
            int idx = i * 256 + t;
            int r   = idx >> 6;
            int k4  = idx & 63;
            float e = (row0 + r < B) ? __ldg(E + row0 + r) : 0.f;
            float4 w = __ldg(ew4 + k4);
            float4 bb = ebf ? __ldg(eb4 + k4) : make_float4(0.f, 0.f, 0.f, 0.f);
            float4 o;
            o.x = actf(e * w.x + bb.x);
            o.y = actf(e * w.y + bb.y);
            o.z = actf(e * w.z + bb.z);
            o.w = actf(e * w.w + bb.w);
            *(float4*)(sA + r * 256 + k4 * 4) = o;
        }
    } else {
        const float4* A4 = (const float4*)A;
        #pragma unroll
        for (int i = 0; i < 8; i++) {
            int idx = i * 256 + t;
            int r   = idx >> 6;
            int k4  = idx & 63;
            float4 v;
            if (row0 + r < B) v = A4[(size_t)(row0 + r) * 64 + k4];
            else              v = make_float4(0.f, 0.f, 0.f, 0.f);
            *(float4*)(sA + r * 256 + k4 * 4) = v;
        }
    }
    __syncthreads();

    // ---- compute: warp rq handles rows rq*4..+3; lane c handles col f0+c ----
    int c  = t & 31;
    int rq = t >> 5;
    ull acc0 = 0, acc1 = 0, acc2 = 0, acc3 = 0;
    const float* wr = sW + c * WST;
    const float* ar = sA + (rq * 4) * 256;
    #pragma unroll 8
    for (int kk = 0; kk < 128; kk++) {
        ull w = *(const ull*)(wr + kk * 2);
        acc0 = ffma2(*(const ull*)(ar + 0 * 256 + kk * 2), w, acc0);
        acc1 = ffma2(*(const ull*)(ar + 1 * 256 + kk * 2), w, acc1);
        acc2 = ffma2(*(const ull*)(ar + 2 * 256 + kk * 2), w, acc2);
        acc3 = ffma2(*(const ull*)(ar + 3 * 256 + kk * 2), w, acc3);
    }

    // ---- epilogue ----
    float o[4] = { pairsum(acc0), pairsum(acc1), pairsum(acc2), pairsum(acc3) };
    float bb = bias ? __ldg(bias + f0 + c) : 0.f;
    float rw = 0.f, rb = 0.f;
    if (mode & 2) {
        rw = __ldg(ewf + f0 + c);
        if (ebf) rb = __ldg(ebf + f0 + c);
    }
    #pragma unroll
    for (int i = 0; i < 4; i++) {
        int row = row0 + rq * 4 + i;
        if (row >= B) continue;
        float v = o[i] + bb;
        if (mode & 2) v += __ldg(E + row) * rw + rb;
        if (mode & 4) v = actf(v);
        C[(size_t)row * 256 + f0 + c] = v;
    }
}

// ---------------- seg helpers (int32 buffer that may really be int64) ----------------
__device__ __forceinline__ int seg_is64(const int* __restrict__ s, int N) {
    return s[N - 1] == 0;   // sorted, max=B-1>0; int64 LE high word at N-1 is 0
}

// ---------------- dot pass: 32 rows/warp, kq register-cached ----------------
__global__ void dot_kernel(const float4* __restrict__ x,
                           const int* __restrict__ seg32,
                           const float* __restrict__ kq,
                           float* __restrict__ dotv,
                           int N) {
    int gw   = (blockIdx.x * blockDim.x + threadIdx.x) >> 5;
    int lane = threadIdx.x & 31;
    int row0 = gw * 32;
    if (row0 >= N) return;
    int st = seg_is64(seg32, N) ? 2 : 1;

    int rlast = row0 + 31 < N ? row0 + 31 : N - 1;
    int b0    = seg32[(size_t)row0 * st];
    int blast = seg32[(size_t)rlast * st];

    if (b0 == blast && row0 + 32 <= N) {
        const float4* kr = (const float4*)kq + (size_t)b0 * 64;
        float4 k0 = kr[lane], k1 = kr[lane + 32];
        float myres = 0.f;
        #pragma unroll
        for (int batch = 0; batch < 4; batch++) {
            float4 xa[8], xb[8];
            #pragma unroll
            for (int r = 0; r < 8; r++) {
                const float4* xr = x + (size_t)(row0 + batch * 8 + r) * 64;
                xa[r] = xr[lane];
                xb[r] = xr[lane + 32];
            }
            float s[8];
            #pragma unroll
            for (int r = 0; r < 8; r++)
                s[r] = dot4(xa[r], k0) + dot4(xb[r], k1);
            #pragma unroll
            for (int o = 16; o; o >>= 1) {
                #pragma unroll
                for (int r = 0; r < 8; r++)
                    s[r] += __shfl_xor_sync(0xffffffffu, s[r], o);
            }
            #pragma unroll
            for (int r = 0; r < 8; r++)
                if (lane == batch * 8 + r) myres = s[r];
        }
        dotv[row0 + lane] = myres;
    } else {
        int nrows = N - row0; if (nrows > 32) nrows = 32;
        int myrow = row0 + lane;
        int rload = myrow < N ? myrow : N - 1;
        int bl = seg32[(size_t)rload * st];
        int bcur = -1;
        float4 k0, k1;
        float myres = 0.f;
        for (int r = 0; r < nrows; r++) {
            int b = __shfl_sync(0xffffffffu, bl, r);
            if (b != bcur) {
                const float4* kr = (const float4*)kq + (size_t)b * 64;
                k0 = kr[lane]; k1 = kr[lane + 32];
                bcur = b;
            }
            const float4* xr = x + (size_t)(row0 + r) * 64;
            float4 a0 = xr[lane], a1 = xr[lane + 32];
            float s = dot4(a0, k0) + dot4(a1, k1);
            #pragma unroll
            for (int o = 16; o; o >>= 1) s += __shfl_xor_sync(0xffffffffu, s, o);
            if (lane == r) myres = s;
        }
        if (myrow < N) dotv[myrow] = myres;
    }
}

// ---------------- segment reduce (deterministic, per-segment block) ----------------
__device__ __forceinline__ int lowerb(const int* __restrict__ s, int n, int v, int st) {
    int lo = 0, hi = n;
    while (lo < hi) {
        int mid = (lo + hi) >> 1;
        if (s[(size_t)mid * st] < v) lo = mid + 1; else hi = mid;
    }
    return lo;
}

__global__ void segreduce_kernel(const int* __restrict__ seg32,
                                 const float* __restrict__ dotv,
                                 float* __restrict__ smax,
                                 float* __restrict__ invnorm,
                                 int N, float scale) {
    __shared__ float red[256];
    __shared__ int sse[2];
    int b = blockIdx.x;
    int t = threadIdx.x;
    if (t == 0) {
        int st = seg_is64(seg32, N) ? 2 : 1;
        sse[0] = lowerb(seg32, N, b, st);
        sse[1] = lowerb(seg32, N, b + 1, st);
    }
    __syncthreads();
    int start = sse[0], end = sse[1];

    float m = -3.4e38f;
    for (int i = start + t; i < end; i += 256) m = fmaxf(m, dotv[i]);
    red[t] = m;
    __syncthreads();
    #pragma unroll
    for (int s = 128; s; s >>= 1) {
        if (t < s) red[t] = fmaxf(red[t], red[t + s]);
        __syncthreads();
    }
    float mx = red[0];
    __syncthreads();

    float ss = 0.f;
    for (int i = start + t; i < end; i += 256) ss += expf((dotv[i] - mx) * scale);
    red[t] = ss;
    __syncthreads();
    #pragma unroll
    for (int s = 128; s; s >>= 1) {
        if (t < s) red[t] += red[t + s];
        __syncthreads();
    }
    if (t == 0) {
        smax[b] = mx;
        invnorm[b] = 1.f / (red[0] + 1e-8f);
    }
}

// ---------------- output pass: 32 rows per warp, vm register-cached ----------------
__global__ void out_kernel(const float* __restrict__ dotv,
                           const int* __restrict__ seg32,
                           const float* __restrict__ vm,
                           const float* __restrict__ smax,
                           const float* __restrict__ invnorm,
                           float4* __restrict__ out,
                           int N, float scale) {
    int gw   = (blockIdx.x * blockDim.x + threadIdx.x) >> 5;
    int lane = threadIdx.x & 31;
    int row0 = gw * 32;
    if (row0 >= N) return;
    int st = seg_is64(seg32, N) ? 2 : 1;

    int myrow = row0 + lane;
    int bl = 0; float cl = 0.f;
    if (myrow < N) {
        bl = seg32[(size_t)myrow * st];
        cl = expf((dotv[myrow] - smax[bl]) * scale) * invnorm[bl];
    }

    int nrows = N - row0; if (nrows > 32) nrows = 32;
    int bcur = -1;
    float4 v0, v1;
    for (int r = 0; r < nrows; r++) {
        int b     = __shfl_sync(0xffffffffu, bl, r);
        float cf  = __shfl_sync(0xffffffffu, cl, r);
        if (b != bcur) {
            const float4* vr = (const float4*)vm + (size_t)b * 64;
            v0 = vr[lane];
            v1 = vr[lane + 32];
            bcur = b;
        }
        float4 o0 = make_float4(v0.x * cf, v0.y * cf, v0.z * cf, v0.w * cf);
        float4 o1 = make_float4(v1.x * cf, v1.y * cf, v1.z * cf, v1.w * cf);
        float4* orow = out + (size_t)(row0 + r) * 64;
        orow[lane]      = o0;
        orow[lane + 32] = o1;
    }
}

// ---------------- launcher ----------------
extern "C" void kernel_launch(void* const* d_in, const int* in_sizes, int n_in,
                              void* d_out, int out_size) {
    int sh = (n_in >= 17) ? 0 : 1;
    const float* x    = (const float*)d_in[0];
    const float* E    = (const float*)d_in[1];
    const int*   seg  = (const int*)  d_in[3 - sh];
    const float* Wq   = (const float*)d_in[4 - sh];
    const float* Wkf  = (const float*)d_in[5 - sh];
    const float* bkf  = (const float*)d_in[6 - sh];
    const float* Wvf  = (const float*)d_in[7 - sh];
    const float* kW1  = (const float*)d_in[8 - sh];
    const float* kb1  = (const float*)d_in[9 - sh];
    const float* kW2  = (const float*)d_in[10 - sh];
    const float* kb2  = (const float*)d_in[11 - sh];
    const float* kWo  = (const float*)d_in[12 - sh];
    const float* kbo  = (const float*)d_in[13 - sh];
    const float* vW1  = (const float*)d_in[14 - sh];
    const float* vW2  = (const float*)d_in[15 - sh];
    const float* vWo  = (const float*)d_in[16 - sh];

    int B = in_sizes[1];
    int N = in_sizes[3 - sh];
    float scale = 1.f / 16.f;   // 1/sqrt(256)

    float *t1k, *t1v, *rk, *rv, *km, *vm, *kq, *wqT, *dotv, *smax, *inv;
    cudaGetSymbolAddress((void**)&t1k, g_t1k);
    cudaGetSymbolAddress((void**)&t1v, g_t1v);
    cudaGetSymbolAddress((void**)&rk,  g_rk);
    cudaGetSymbolAddress((void**)&rv,  g_rv);
    cudaGetSymbolAddress((void**)&km,  g_km);
    cudaGetSymbolAddress((void**)&vm,  g_vm);
    cudaGetSymbolAddress((void**)&kq,  g_kq);
    cudaGetSymbolAddress((void**)&wqT, g_wqT);
    cudaGetSymbolAddress((void**)&dotv, g_dot);
    cudaGetSymbolAddress((void**)&smax, g_smax);
    cudaGetSymbolAddress((void**)&inv,  g_inv);

    const int LS = (32 * WST + 32 * 256) * (int)sizeof(float);   // 65792 B
    cudaFuncSetAttribute(layer_kernel, cudaFuncAttributeMaxDynamicSharedMemorySize, LS);

    int rowTiles = (B + 31) / 32;

    // 0) Wq transpose (off the critical math; needed by L4)
    transpose256_kernel<<<64, 256>>>(Wq, wqT);

    // 1) L1: t1 = act( entry(E) @ W1^T + b1 )
    dim3 lg(8, rowTiles, 2);
    layer_kernel<<<lg, 256, LS>>>(nullptr, nullptr, kW1, vW1, kb1, nullptr, E,
                                  Wkf, bkf, Wvf, nullptr, t1k, t1v, B, 1 | 4);
    // 2) L2: r = act( rank1(E) + t1 @ W2^T + b2 )
    layer_kernel<<<lg, 256, LS>>>(t1k, t1v, kW2, vW2, kb2, nullptr, E,
                                  Wkf, bkf, Wvf, nullptr, rk, rv, B, 2 | 4);
    // 3) L3: km = r @ Wo^T + bo ; vm = r @ vWo^T
    layer_kernel<<<lg, 256, LS>>>(rk, rv, kWo, vWo, kbo, nullptr, E,
                                  nullptr, nullptr, nullptr, nullptr, km, vm, B, 0);
    // 4) L4 (k only): kq = km @ Wq  == transposed-GEMM with W = WqT
    dim3 lg4(8, rowTiles, 1);
    layer_kernel<<<lg4, 256, LS>>>(km, km, wqT, wqT, nullptr, nullptr, E,
                                   nullptr, nullptr, nullptr, nullptr, kq, kq, B, 0);

    // 5) dot pass
    {
        int warps = (N + 31) / 32;
        int blocks = (warps * 32 + 255) / 256;
        dot_kernel<<<blocks, 256>>>((const float4*)x, seg, kq, dotv, N);
    }
    // 6) segment reduce
    segreduce_kernel<<<B, 256>>>(seg, dotv, smax, inv, N, scale);
    // 7) output pass
    {
        int warps = (N + 31) / 32;
        int blocks = (warps * 32 + 255) / 256;
        out_kernel<<<blocks, 256>>>(dotv, seg, vm, smax, inv, (float4*)d_out, N, scale);
    }
}

// round 10
// speedup vs baseline: 1.2821x; 1.0800x over previous
#include <cuda_runtime.h>
#include <math.h>

#define FDIM 256
#define BMAX 1024
#define NMAX 1048576
#define WST 260           // sW stride (256 data + 4 pad): 16B-aligned rows, conflict-free LDS.128

typedef unsigned long long ull;

// ---------------- scratch (static device globals; no allocation) ----------------
__device__ __align__(128) float g_t1k[BMAX * FDIM];
__device__ __align__(128) float g_t1v[BMAX * FDIM];
__device__ __align__(128) float g_rk [BMAX * FDIM];
__device__ __align__(128) float g_rv [BMAX * FDIM];
__device__ __align__(128) float g_km [BMAX * FDIM];
__device__ __align__(128) float g_vm [BMAX * FDIM];
__device__ __align__(128) float g_kq [BMAX * FDIM];
__device__ __align__(128) float g_wqT[FDIM * FDIM];
__device__ __align__(128) float g_dot[NMAX];
__device__ __align__(128) float g_smax[BMAX];
__device__ __align__(128) float g_inv [BMAX];

__device__ __forceinline__ float actf(float x) {
    return x / (1.0f + expf(-1.702f * x));
}
__device__ __forceinline__ ull ffma2(ull a, ull b, ull c) {
    ull d;
    asm("fma.rn.f32x2 %0, %1, %2, %3;" : "=l"(d) : "l"(a), "l"(b), "l"(c));
    return d;
}
__device__ __forceinline__ float pairsum(ull v) {
    float2 f = *(float2*)&v;
    return f.x + f.y;
}
__device__ __forceinline__ float dot4(float4 a, float4 b) {
    return a.x * b.x + a.y * b.y + a.z * b.z + a.w * b.w;
}

// ---------------- transpose 256x256 (for Wq) ----------------
__global__ void transpose256_kernel(const float* __restrict__ in, float* __restrict__ out) {
    __shared__ float tile[32][33];
    int bx = (blockIdx.x & 7) * 32;
    int by = (blockIdx.x >> 3) * 32;
    int tx = threadIdx.x & 31, ty = threadIdx.x >> 5;
    #pragma unroll
    for (int i = 0; i < 32; i += 8)
        tile[ty + i][tx] = in[(size_t)(by + ty + i) * 256 + bx + tx];
    __syncthreads();
    #pragma unroll
    for (int i = 0; i < 32; i += 8)
        out[(size_t)(bx + ty + i) * 256 + by + tx] = tile[tx][ty + i];
}

// ================= col-tiled layer GEMM =================
// C[row0+r][f0+c] = post( A[row0+r,:] . W[f0+c,:] + bias[f0+c] )
// grid: (8 colTiles, rowTiles, 2 branches).  block 256: warp = 4 rows, lane = col.
// mode bits: 1 = A is entry rank1 act(E*ewf+ebf); 2 = add rank1 residual in epilogue;
//            4 = apply act.
__global__ __launch_bounds__(256)
void layer_kernel(const float* __restrict__ A0, const float* __restrict__ A1,
                  const float* __restrict__ W0, const float* __restrict__ W1,
                  const float* __restrict__ b0, const float* __restrict__ b1,
                  const float* __restrict__ E,
                  const float* __restrict__ ef0, const float* __restrict__ eb0,
                  const float* __restrict__ ef1, const float* __restrict__ eb1,
                  float* __restrict__ C0, float* __restrict__ C1,
                  int B, int mode) {
    extern __shared__ __align__(16) float sm[];
    float* sW = sm;                 // 32 x WST
    float* sA = sm + 32 * WST;      // 32 x 256

    int br = blockIdx.z;
    const float* A    = br ? A1 : A0;
    const float* W    = br ? W1 : W0;
    const float* bias = br ? b1 : b0;
    const float* ewf  = br ? ef1 : ef0;
    const float* ebf  = br ? eb1 : eb0;
    float*       C    = br ? C1 : C0;

    int t    = threadIdx.x;
    int f0   = blockIdx.x * 32;
    int row0 = blockIdx.y * 32;

    // ---- stage W tile: rows f0..f0+31, all 256 k (coalesced LDG.128 -> STS.128) ----
    {
        const float4* W4 = (const float4*)W;
        #pragma unroll
        for (int i = 0; i < 8; i++) {
            int idx = i * 256 + t;      // 0..2047
            int row = idx >> 6;
            int k4  = idx & 63;
            float4 v = W4[(size_t)(f0 + row) * 64 + k4];
            *(float4*)(sW + row * WST + k4 * 4) = v;
        }
    }

    // ---- stage A tile: rows row0..row0+31 ----
    if (mode & 1) {
        const float4* ew4 = (const float4*)ewf;
        const float4* eb4 = (const float4*)ebf;
        #pragma unroll
        for (int i = 0; i < 8; i++) {
            int idx = i * 256 + t;
            int r   = idx >> 6;
            int k4  = idx & 63;
            float e = (row0 + r < B) ? __ldg(E + row0 + r) : 0.f;
            float4 w = __ldg(ew4 + k4);
            float4 bb = ebf ? __ldg(eb4 + k4) : make_float4(0.f, 0.f, 0.f, 0.f);
            float4 o;
            o.x = actf(e * w.x + bb.x);
            o.y = actf(e * w.y + bb.y);
            o.z = actf(e * w.z + bb.z);
            o.w = actf(e * w.w + bb.w);
            *(float4*)(sA + r * 256 + k4 * 4) = o;
        }
    } else {
        const float4* A4 = (const float4*)A;
        #pragma unroll
        for (int i = 0; i < 8; i++) {
            int idx = i * 256 + t;
            int r   = idx >> 6;
            int k4  = idx & 63;
            float4 v;
            if (row0 + r < B) v = A4[(size_t)(row0 + r) * 64 + k4];
            else              v = make_float4(0.f, 0.f, 0.f, 0.f);
            *(float4*)(sA + r * 256 + k4 * 4) = v;
        }
    }
    __syncthreads();

    // ---- compute: warp rq -> rows rq*4..+3; lane c -> col f0+c ----
    // LDS.128 for both operands; 2 independent f32x2 chains per row.
    int c  = t & 31;
    int rq = t >> 5;
    const float* wr = sW + c * WST;
    const float* ar = sA + (rq * 4) * 256;

    ull acc[4][2] = {{0,0},{0,0},{0,0},{0,0}};
    #pragma unroll 8
    for (int kk = 0; kk < 64; kk++) {        // 4 k per iter
        ulonglong2 w = *(const ulonglong2*)(wr + kk * 4);
        #pragma unroll
        for (int r = 0; r < 4; r++) {
            ulonglong2 a = *(const ulonglong2*)(ar + r * 256 + kk * 4);
            acc[r][0] = ffma2(a.x, w.x, acc[r][0]);
            acc[r][1] = ffma2(a.y, w.y, acc[r][1]);
        }
    }

    // ---- epilogue ----
    float o[4];
    #pragma unroll
    for (int r = 0; r < 4; r++)
        o[r] = pairsum(acc[r][0]) + pairsum(acc[r][1]);

    float bb = bias ? __ldg(bias + f0 + c) : 0.f;
    float rw = 0.f, rb = 0.f;
    if (mode & 2) {
        rw = __ldg(ewf + f0 + c);
        if (ebf) rb = __ldg(ebf + f0 + c);
    }
    #pragma unroll
    for (int i = 0; i < 4; i++) {
        int row = row0 + rq * 4 + i;
        if (row >= B) continue;
        float v = o[i] + bb;
        if (mode & 2) v += __ldg(E + row) * rw + rb;
        if (mode & 4) v = actf(v);
        C[(size_t)row * 256 + f0 + c] = v;
    }
}

// ---------------- seg helpers (int32 buffer that may really be int64) ----------------
__device__ __forceinline__ int seg_is64(const int* __restrict__ s, int N) {
    return s[N - 1] == 0;   // sorted, max=B-1>0; int64 LE high word at N-1 is 0
}

// ---------------- dot pass: 32 rows/warp, kq register-cached, streaming x ------------
__global__ void dot_kernel(const float4* __restrict__ x,
                           const int* __restrict__ seg32,
                           const float* __restrict__ kq,
                           float* __restrict__ dotv,
                           int N) {
    int gw   = (blockIdx.x * blockDim.x + threadIdx.x) >> 5;
    int lane = threadIdx.x & 31;
    int row0 = gw * 32;
    if (row0 >= N) return;
    int st = seg_is64(seg32, N) ? 2 : 1;

    int rlast = row0 + 31 < N ? row0 + 31 : N - 1;
    int b0    = seg32[(size_t)row0 * st];
    int blast = seg32[(size_t)rlast * st];

    if (b0 == blast && row0 + 32 <= N) {
        const float4* kr = (const float4*)kq + (size_t)b0 * 64;
        float4 k0 = kr[lane], k1 = kr[lane + 32];
        float myres = 0.f;
        #pragma unroll
        for (int batch = 0; batch < 4; batch++) {
            float4 xa[8], xb[8];
            #pragma unroll
            for (int r = 0; r < 8; r++) {
                const float4* xr = x + (size_t)(row0 + batch * 8 + r) * 64;
                xa[r] = __ldcs(xr + lane);
                xb[r] = __ldcs(xr + lane + 32);
            }
            float s[8];
            #pragma unroll
            for (int r = 0; r < 8; r++)
                s[r] = dot4(xa[r], k0) + dot4(xb[r], k1);
            #pragma unroll
            for (int o = 16; o; o >>= 1) {
                #pragma unroll
                for (int r = 0; r < 8; r++)
                    s[r] += __shfl_xor_sync(0xffffffffu, s[r], o);
            }
            #pragma unroll
            for (int r = 0; r < 8; r++)
                if (lane == batch * 8 + r) myres = s[r];
        }
        dotv[row0 + lane] = myres;
    } else {
        int nrows = N - row0; if (nrows > 32) nrows = 32;
        int myrow = row0 + lane;
        int rload = myrow < N ? myrow : N - 1;
        int bl = seg32[(size_t)rload * st];
        int bcur = -1;
        float4 k0, k1;
        float myres = 0.f;
        for (int r = 0; r < nrows; r++) {
            int b = __shfl_sync(0xffffffffu, bl, r);
            if (b != bcur) {
                const float4* kr = (const float4*)kq + (size_t)b * 64;
                k0 = kr[lane]; k1 = kr[lane + 32];
                bcur = b;
            }
            const float4* xr = x + (size_t)(row0 + r) * 64;
            float4 a0 = __ldcs(xr + lane), a1 = __ldcs(xr + lane + 32);
            float s = dot4(a0, k0) + dot4(a1, k1);
            #pragma unroll
            for (int o = 16; o; o >>= 1) s += __shfl_xor_sync(0xffffffffu, s, o);
            if (lane == r) myres = s;
        }
        if (myrow < N) dotv[myrow] = myres;
    }
}

// ---------------- segment reduce (deterministic, per-segment block) ----------------
__device__ __forceinline__ int lowerb(const int* __restrict__ s, int n, int v, int st) {
    int lo = 0, hi = n;
    while (lo < hi) {
        int mid = (lo + hi) >> 1;
        if (s[(size_t)mid * st] < v) lo = mid + 1; else hi = mid;
    }
    return lo;
}

__global__ void segreduce_kernel(const int* __restrict__ seg32,
                                 const float* __restrict__ dotv,
                                 float* __restrict__ smax,
                                 float* __restrict__ invnorm,
                                 int N, float scale) {
    __shared__ float red[256];
    __shared__ int sse[2];
    int b = blockIdx.x;
    int t = threadIdx.x;
    if (t == 0) {
        int st = seg_is64(seg32, N) ? 2 : 1;
        sse[0] = lowerb(seg32, N, b, st);
        sse[1] = lowerb(seg32, N, b + 1, st);
    }
    __syncthreads();
    int start = sse[0], end = sse[1];

    float m = -3.4e38f;
    for (int i = start + t; i < end; i += 256) m = fmaxf(m, dotv[i]);
    red[t] = m;
    __syncthreads();
    #pragma unroll
    for (int s = 128; s; s >>= 1) {
        if (t < s) red[t] = fmaxf(red[t], red[t + s]);
        __syncthreads();
    }
    float mx = red[0];
    __syncthreads();

    float ss = 0.f;
    for (int i = start + t; i < end; i += 256) ss += expf((dotv[i] - mx) * scale);
    red[t] = ss;
    __syncthreads();
    #pragma unroll
    for (int s = 128; s; s >>= 1) {
        if (t < s) red[t] += red[t + s];
        __syncthreads();
    }
    if (t == 0) {
        smax[b] = mx;
        invnorm[b] = 1.f / (red[0] + 1e-8f);
    }
}

// ---------------- output pass: 32 rows/warp, vm register-cached, streaming stores ----
__global__ void out_kernel(const float* __restrict__ dotv,
                           const int* __restrict__ seg32,
                           const float* __restrict__ vm,
                           const float* __restrict__ smax,
                           const float* __restrict__ invnorm,
                           float4* __restrict__ out,
                           int N, float scale) {
    int gw   = (blockIdx.x * blockDim.x + threadIdx.x) >> 5;
    int lane = threadIdx.x & 31;
    int row0 = gw * 32;
    if (row0 >= N) return;
    int st = seg_is64(seg32, N) ? 2 : 1;

    int myrow = row0 + lane;
    int bl = 0; float cl = 0.f;
    if (myrow < N) {
        bl = seg32[(size_t)myrow * st];
        cl = expf((dotv[myrow] - smax[bl]) * scale) * invnorm[bl];
    }

    int nrows = N - row0; if (nrows > 32) nrows = 32;
    int bcur = -1;
    float4 v0, v1;
    for (int r = 0; r < nrows; r++) {
        int b     = __shfl_sync(0xffffffffu, bl, r);
        float cf  = __shfl_sync(0xffffffffu, cl, r);
        if (b != bcur) {
            const float4* vr = (const float4*)vm + (size_t)b * 64;
            v0 = vr[lane];
            v1 = vr[lane + 32];
            bcur = b;
        }
        float4 o0 = make_float4(v0.x * cf, v0.y * cf, v0.z * cf, v0.w * cf);
        float4 o1 = make_float4(v1.x * cf, v1.y * cf, v1.z * cf, v1.w * cf);
        float4* orow = out + (size_t)(row0 + r) * 64;
        __stcs(orow + lane, o0);
        __stcs(orow + lane + 32, o1);
    }
}

// ---------------- launcher ----------------
extern "C" void kernel_launch(void* const* d_in, const int* in_sizes, int n_in,
                              void* d_out, int out_size) {
    int sh = (n_in >= 17) ? 0 : 1;
    const float* x    = (const float*)d_in[0];
    const float* E    = (const float*)d_in[1];
    const int*   seg  = (const int*)  d_in[3 - sh];
    const float* Wq   = (const float*)d_in[4 - sh];
    const float* Wkf  = (const float*)d_in[5 - sh];
    const float* bkf  = (const float*)d_in[6 - sh];
    const float* Wvf  = (const float*)d_in[7 - sh];
    const float* kW1  = (const float*)d_in[8 - sh];
    const float* kb1  = (const float*)d_in[9 - sh];
    const float* kW2  = (const float*)d_in[10 - sh];
    const float* kb2  = (const float*)d_in[11 - sh];
    const float* kWo  = (const float*)d_in[12 - sh];
    const float* kbo  = (const float*)d_in[13 - sh];
    const float* vW1  = (const float*)d_in[14 - sh];
    const float* vW2  = (const float*)d_in[15 - sh];
    const float* vWo  = (const float*)d_in[16 - sh];

    int B = in_sizes[1];
    int N = in_sizes[3 - sh];
    float scale = 1.f / 16.f;   // 1/sqrt(256)

    float *t1k, *t1v, *rk, *rv, *km, *vm, *kq, *wqT, *dotv, *smax, *inv;
    cudaGetSymbolAddress((void**)&t1k, g_t1k);
    cudaGetSymbolAddress((void**)&t1v, g_t1v);
    cudaGetSymbolAddress((void**)&rk,  g_rk);
    cudaGetSymbolAddress((void**)&rv,  g_rv);
    cudaGetSymbolAddress((void**)&km,  g_km);
    cudaGetSymbolAddress((void**)&vm,  g_vm);
    cudaGetSymbolAddress((void**)&kq,  g_kq);
    cudaGetSymbolAddress((void**)&wqT, g_wqT);
    cudaGetSymbolAddress((void**)&dotv, g_dot);
    cudaGetSymbolAddress((void**)&smax, g_smax);
    cudaGetSymbolAddress((void**)&inv,  g_inv);

    const int LS = (32 * WST + 32 * 256) * (int)sizeof(float);   // 66048 B
    cudaFuncSetAttribute(layer_kernel, cudaFuncAttributeMaxDynamicSharedMemorySize, LS);

    int rowTiles = (B + 31) / 32;

    // 0) Wq transpose (needed by L4)
    transpose256_kernel<<<64, 256>>>(Wq, wqT);

    // 1) L1: t1 = act( entry(E) @ W1^T + b1 )
    dim3 lg(8, rowTiles, 2);
    layer_kernel<<<lg, 256, LS>>>(nullptr, nullptr, kW1, vW1, kb1, nullptr, E,
                                  Wkf, bkf, Wvf, nullptr, t1k, t1v, B, 1 | 4);
    // 2) L2: r = act( rank1(E) + t1 @ W2^T + b2 )
    layer_kernel<<<lg, 256, LS>>>(t1k, t1v, kW2, vW2, kb2, nullptr, E,
                                  Wkf, bkf, Wvf, nullptr, rk, rv, B, 2 | 4);
    // 3) L3: km = r @ Wo^T + bo ; vm = r @ vWo^T
    layer_kernel<<<lg, 256, LS>>>(rk, rv, kWo, vWo, kbo, nullptr, E,
                                  nullptr, nullptr, nullptr, nullptr, km, vm, B, 0);
    // 4) L4 (k only): kq = km @ Wq  == transposed-GEMM with W = WqT
    dim3 lg4(8, rowTiles, 1);
    layer_kernel<<<lg4, 256, LS>>>(km, km, wqT, wqT, nullptr, nullptr, E,
                                   nullptr, nullptr, nullptr, nullptr, kq, kq, B, 0);

    // 5) dot pass
    {
        int warps = (N + 31) / 32;
        int blocks = (warps * 32 + 255) / 256;
        dot_kernel<<<blocks, 256>>>((const float4*)x, seg, kq, dotv, N);
    }
    // 6) segment reduce
    segreduce_kernel<<<B, 256>>>(seg, dotv, smax, inv, N, scale);
    // 7) output pass
    {
        int warps = (N + 31) / 32;
        int blocks = (warps * 32 + 255) / 256;
        out_kernel<<<blocks, 256>>>(dotv, seg, vm, smax, inv, (float4*)d_out, N, scale);
    }
}